// round 3
// baseline (speedup 1.0000x reference)
#include <cuda_runtime.h>
#include <math.h>

// Problem constants
#define TK   16384          // tokens (4*4096)
#define HD   7168           // hidden
#define NE   256            // experts
#define NG   8              // groups
#define BT   32             // tokens per block
#define BK   32             // k-chunk
#define NCH  (HD / BK)      // 224 chunks

// smem pool: GEMM needs As[32*33] + Bs[256*33] = 9504 floats,
// routing reuses the first 32*257 = 8224 floats for logits.
#define POOL_FLOATS 9504

// ---------------------------------------------------------------------------
// Fast-math-immune, ~1-ulp sigmoid. The harness compiles with
// --use_fast_math, which degrades expf/division to approximate intrinsics;
// near-tie expert ranking decisions need correctly-rounded scores.
// exp via Cody-Waite range reduction + degree-7 Taylor (all fmaf),
// 1/(1+e) via __frcp_rn (correctly rounded; == division for numerator 1.0).
// ---------------------------------------------------------------------------
__device__ __forceinline__ float sigmoid_acc(float x)
{
    float t = -x;
    // clamp (never hit for |logit| <~ 4, protects the 2^n scale)
    t = fminf(fmaxf(t, -80.0f), 80.0f);
    const float LOG2E   = 1.4426950408889634f;
    const float LN2_HI  = 0.693359375f;        // 11-bit mantissa: n*LN2_HI exact
    const float LN2_LO  = -2.12194440e-4f;
    float n = rintf(t * LOG2E);
    float r = fmaf(n, -LN2_HI, t);
    r = fmaf(n, -LN2_LO, r);                   // r in [-0.3466, 0.3466]
    // e^r, Taylor degree 7 (trunc err ~5e-9)
    float p = 1.9841270e-4f;
    p = fmaf(p, r, 1.3888889e-3f);
    p = fmaf(p, r, 8.3333333e-3f);
    p = fmaf(p, r, 4.1666667e-2f);
    p = fmaf(p, r, 0.16666667f);
    p = fmaf(p, r, 0.5f);
    p = fmaf(p, r, 1.0f);
    p = fmaf(p, r, 1.0f);
    float scale = __int_as_float(((int)n + 127) << 23);
    float e = p * scale;                       // e = exp(-x)
    return __frcp_rn(1.0f + e);                // 1/(1+e), correctly rounded
}

__global__ __launch_bounds__(256, 2)
void moe_gate_kernel(const float* __restrict__ X,
                     const float* __restrict__ W,
                     const float* __restrict__ BIAS,
                     float* __restrict__ out)
{
    __shared__ float pool[POOL_FLOATS];
    float* As = pool;             // [32][33]
    float* Bs = pool + BT * 33;   // [256][33]

    const int tid = threadIdx.x;
    const int tx  = tid & 31;     // 0..31 (expert lane)
    const int ty  = tid >> 5;     // 0..7  (warp id)
    const int t0  = blockIdx.x * BT;

    // ------------------------------------------------------------------
    // Phase 1: GEMM  logits[32,256] = X[t0:t0+32, :] * W^T
    // micro-tile: token t = ty + 8*i (i<4), expert e = tx + 32*j (j<8)
    // Three-level accumulation (chunk of 32 -> mid of 8 chunks -> total)
    // keeps fp32 logit error ~1e-7.
    // ------------------------------------------------------------------
    float acc[4][8], mid[4][8];
    #pragma unroll
    for (int i = 0; i < 4; i++)
        #pragma unroll
        for (int j = 0; j < 8; j++) { acc[i][j] = 0.0f; mid[i][j] = 0.0f; }

    // global-load mapping (one float4 of A, eight float4 of B per thread)
    const int a_t = tid >> 3;              // token row 0..31
    const int a_k = (tid & 7) * 4;         // k offset within chunk
    const int b_e0 = tid >> 3;             // expert row base 0..31 (stride 32 over r)
    const int b_k = (tid & 7) * 4;

    const float* xrow = X + (size_t)(t0 + a_t) * HD + a_k;

    float4 aReg;
    float4 bReg[8];

    // prefetch chunk 0
    aReg = *(const float4*)(xrow);
    #pragma unroll
    for (int r = 0; r < 8; r++)
        bReg[r] = *(const float4*)(W + (size_t)(b_e0 + 32 * r) * HD + b_k);

    for (int c = 0; c < NCH; c++) {
        // commit prefetched chunk to smem
        As[a_t * 33 + a_k + 0] = aReg.x;
        As[a_t * 33 + a_k + 1] = aReg.y;
        As[a_t * 33 + a_k + 2] = aReg.z;
        As[a_t * 33 + a_k + 3] = aReg.w;
        #pragma unroll
        for (int r = 0; r < 8; r++) {
            int e = b_e0 + 32 * r;
            Bs[e * 33 + b_k + 0] = bReg[r].x;
            Bs[e * 33 + b_k + 1] = bReg[r].y;
            Bs[e * 33 + b_k + 2] = bReg[r].z;
            Bs[e * 33 + b_k + 3] = bReg[r].w;
        }
        __syncthreads();

        // prefetch next chunk (overlaps with compute below)
        if (c + 1 < NCH) {
            const int off = (c + 1) * BK;
            aReg = *(const float4*)(xrow + off);
            #pragma unroll
            for (int r = 0; r < 8; r++)
                bReg[r] = *(const float4*)(W + (size_t)(b_e0 + 32 * r) * HD + b_k + off);
        }

        // compute: chunk-local accumulators
        float cacc[4][8];
        #pragma unroll
        for (int i = 0; i < 4; i++)
            #pragma unroll
            for (int j = 0; j < 8; j++)
                cacc[i][j] = 0.0f;

        #pragma unroll 8
        for (int k = 0; k < BK; k++) {
            float a[4], b[8];
            #pragma unroll
            for (int i = 0; i < 4; i++) a[i] = As[(ty + 8 * i) * 33 + k];
            #pragma unroll
            for (int j = 0; j < 8; j++) b[j] = Bs[(tx + 32 * j) * 33 + k];
            #pragma unroll
            for (int i = 0; i < 4; i++)
                #pragma unroll
                for (int j = 0; j < 8; j++)
                    cacc[i][j] = fmaf(a[i], b[j], cacc[i][j]);
        }

        // fold chunk sum into mid accumulator; fold mid into total every 8 chunks
        #pragma unroll
        for (int i = 0; i < 4; i++)
            #pragma unroll
            for (int j = 0; j < 8; j++)
                mid[i][j] += cacc[i][j];
        if ((c & 7) == 7) {
            #pragma unroll
            for (int i = 0; i < 4; i++)
                #pragma unroll
                for (int j = 0; j < 8; j++) { acc[i][j] += mid[i][j]; mid[i][j] = 0.0f; }
        }

        __syncthreads();
    }

    // ------------------------------------------------------------------
    // Phase 2: stash logits in smem (stride 257, conflict-free)
    // ------------------------------------------------------------------
    float* S = pool;  // [32][257], 8224 floats
    #pragma unroll
    for (int i = 0; i < 4; i++)
        #pragma unroll
        for (int j = 0; j < 8; j++)
            S[(ty + 8 * i) * 257 + tx + 32 * j] = acc[i][j];
    __syncthreads();

    // ------------------------------------------------------------------
    // Phase 3: routing. Each warp handles 4 tokens.
    // lane `tx` owns experts e = g*32 + tx for g in [0,8) (one per group).
    // ------------------------------------------------------------------
    const unsigned FULL = 0xffffffffu;
    for (int rr = 0; rr < 4; rr++) {
        const int tl = ty * 4 + rr;
        const int tg = t0 + rr * 8 + ty;   // NOTE: see below, keep mapping consistent
        // use the straightforward mapping: token tl of this block
        const int tok = t0 + tl;
        (void)tg;

        float sfc[8];  // sigmoid(logit) + bias  (scores_for_choice)
        #pragma unroll
        for (int g = 0; g < 8; g++) {
            float lg = S[tl * 257 + g * 32 + tx];
            float s = sigmoid_acc(lg);
            sfc[g] = s + __ldg(&BIAS[g * 32 + tx]);
        }

        // per-group score = sum of top-2 sfc within each 32-expert group
        float gs[8];
        #pragma unroll
        for (int g = 0; g < 8; g++) {
            float m1 = sfc[g], m2 = -3.4e38f;
            #pragma unroll
            for (int off = 16; off > 0; off >>= 1) {
                float o1 = __shfl_xor_sync(FULL, m1, off);
                float o2 = __shfl_xor_sync(FULL, m2, off);
                if (o1 > m1) { m2 = fmaxf(m1, o2); m1 = o1; }
                else         { m2 = fmaxf(m2, o1); }
            }
            gs[g] = m1 + m2;   // identical across lanes
        }

        // top-4 groups (ties -> lower group index; strict > preserves that)
        unsigned gmask = 0;
        #pragma unroll
        for (int it = 0; it < 4; it++) {
            float best = -3.4e38f; int bg = 0;
            #pragma unroll
            for (int g = 0; g < 8; g++) {
                bool free_g = !((gmask >> g) & 1);
                if (free_g && gs[g] > best) { best = gs[g]; bg = g; }
            }
            gmask |= (1u << bg);
        }

        // masked candidates (masked-out experts = 0.0, matching reference)
        float val[8];
        #pragma unroll
        for (int g = 0; g < 8; g++)
            val[g] = ((gmask >> g) & 1) ? sfc[g] : 0.0f;

        // iterative top-8 (descending, ties -> lower expert index)
        float wts[8]; int ids[8]; float wsum = 0.0f;
        #pragma unroll
        for (int k = 0; k < 8; k++) {
            float bv = -3.4e38f; int be = 1 << 30;
            #pragma unroll
            for (int g = 0; g < 8; g++) {
                int e = g * 32 + tx;
                bool better = (val[g] > bv) || (val[g] == bv && e < be);
                if (better) { bv = val[g]; be = e; }
            }
            #pragma unroll
            for (int off = 16; off > 0; off >>= 1) {
                float ov = __shfl_xor_sync(FULL, bv, off);
                int   oe = __shfl_xor_sync(FULL, be, off);
                if (ov > bv || (ov == bv && oe < be)) { bv = ov; be = oe; }
            }
            // be now uniform across the warp
            float lg = S[tl * 257 + be];                 // broadcast read
            float wgt = sigmoid_acc(lg);                 // raw sigmoid score
            wts[k] = wgt; ids[k] = be; wsum += wgt;
            const int cg = be >> 5, cl = be & 31;
            #pragma unroll
            for (int g = 0; g < 8; g++)
                if (g == cg && tx == cl) val[g] = -3.4e38f;
        }

        if (tx == 0) {
            float denom = wsum + 1e-20f;
            #pragma unroll
            for (int k = 0; k < 8; k++) {
                out[(size_t)tok * 8 + k] = (float)ids[k];
                // match reference op order: (w / denom) * 2.5
                out[(size_t)TK * 8 + (size_t)tok * 8 + k] = (wts[k] / denom) * 2.5f;
            }
        }
    }
}

extern "C" void kernel_launch(void* const* d_in, const int* in_sizes, int n_in,
                              void* d_out, int out_size)
{
    const float* X    = (const float*)d_in[0];   // [4,4096,7168] fp32
    const float* W    = (const float*)d_in[1];   // [256,7168]    fp32
    const float* BIAS = (const float*)d_in[2];   // [256]         fp32
    float* out = (float*)d_out;                  // [2*16384*8]   fp32 (idx then weights)

    moe_gate_kernel<<<TK / BT, 256>>>(X, W, BIAS, out);
}